// round 3
// baseline (speedup 1.0000x reference)
#include <cuda_runtime.h>
#include <cuda_bf16.h>
#include <cstdint>

#define SEQ   2048
#define D_IN  300
#define U     150
#define NZ    600      // 4 gates * U
#define KP    152      // padded recurrence depth (multiple of 4)
#define H1    300

// ------------------------- scratch (static device memory; no allocs) ---------
__device__ float g_Z[2][SEQ][NZ];        // precomputed x@Wk + b, per direction
__device__ float g_hidden[SEQ][H1];      // [hf | hb] concat
__device__ float g_out[SEQ][H1];         // hidden @ W1 + b1
__device__ float g_H[H1];                // final weighted sum

// ------------------------- small PTX helpers ---------------------------------
__device__ __forceinline__ uint32_t smem_u32(const void* p) {
    return (uint32_t)__cvta_generic_to_shared(p);
}
__device__ __forceinline__ uint32_t mapa_rank(uint32_t addr, uint32_t r) {
    uint32_t out;
    asm("mapa.shared::cluster.u32 %0, %1, %2;" : "=r"(out) : "r"(addr), "r"(r));
    return out;
}
__device__ __forceinline__ void st_cluster_f32(uint32_t addr, float v) {
    asm volatile("st.shared::cluster.f32 [%0], %1;" :: "r"(addr), "f"(v) : "memory");
}
__device__ __forceinline__ void cluster_sync_() {
    asm volatile("barrier.cluster.arrive.aligned;" ::: "memory");
    asm volatile("barrier.cluster.wait.aligned;" ::: "memory");
}
__device__ __forceinline__ uint32_t my_cluster_rank() {
    uint32_t r;
    asm("mov.u32 %0, %%cluster_ctarank;" : "=r"(r));
    return r;
}

// ============================================================================
// Kernel 0: zero the accumulator for H
// ============================================================================
__global__ void zeroH_kernel() {
    if (threadIdx.x < H1) g_H[threadIdx.x] = 0.f;
}

// ============================================================================
// Kernel 1: gather embedding row + precompute Z[dir][t][:] = x_t @ Wk + b
// grid (SEQ, 2), block 160 (150 active, 4 outputs each)
// ============================================================================
__global__ void __launch_bounds__(160) embZ_kernel(
    const int* __restrict__ sentence, const float* __restrict__ E,
    const float* __restrict__ Wk_f, const float* __restrict__ b_f,
    const float* __restrict__ Wk_b, const float* __restrict__ b_b)
{
    __shared__ float x_sh[D_IN];
    const int t = blockIdx.x;
    const int dir = blockIdx.y;
    const int tok = sentence[t];
    for (int d = threadIdx.x; d < D_IN; d += blockDim.x)
        x_sh[d] = E[(size_t)tok * D_IN + d];
    __syncthreads();

    const float* __restrict__ Wk = dir ? Wk_b : Wk_f;
    const float* __restrict__ b  = dir ? b_b  : b_f;

    const int j = threadIdx.x * 4;
    if (j < NZ) {
        float4 acc = *(const float4*)(b + j);
        #pragma unroll 4
        for (int d = 0; d < D_IN; d++) {
            const float x = x_sh[d];
            const float4 wv = *(const float4*)(Wk + d * NZ + j);
            acc.x = fmaf(x, wv.x, acc.x);
            acc.y = fmaf(x, wv.y, acc.y);
            acc.z = fmaf(x, wv.z, acc.z);
            acc.w = fmaf(x, wv.w, acc.w);
        }
        *(float4*)&g_Z[dir][t][j] = acc;
    }
}

// ============================================================================
// Kernel 2: the sequential bidirectional LSTM recurrence.
// grid (4, 2), cluster (4,1,1): blockIdx.y = direction, cluster rank = gate.
// Each CTA holds its gate's 150x150 slice of Wr REGISTER-RESIDENT
// (150 weights per thread, thread = gate output index). Each step:
//   z = Zpre + h . w  ->  activate  ->  DSMEM broadcast to all 4 CTAs
//   -> cluster.sync -> every CTA redundantly updates (c, h) -> local barrier.
// ============================================================================
__global__ void __cluster_dims__(4, 1, 1) __launch_bounds__(160, 1)
lstm_rec_kernel(const float* __restrict__ Wr_f, const float* __restrict__ Wr_b)
{
    __shared__ __align__(16) float h_sh[KP];
    __shared__ float gates_sh[2][4][U];    // double-buffered activated gates

    const int tid  = threadIdx.x;
    const uint32_t rank = my_cluster_rank();   // 0=i, 1=f, 2=g(cell), 3=o
    const int dir  = blockIdx.y;
    const float* __restrict__ Wr = dir ? Wr_b : Wr_f;

    // init shared h to zero (padded tail too)
    if (tid < KP) h_sh[tid] = 0.f;

    // register-resident weights: column (rank*U + tid) of Wr, padded to KP
    float w[KP];
    if (tid < U) {
        #pragma unroll
        for (int k = 0; k < U; k++) w[k] = Wr[k * NZ + rank * U + tid];
        w[150] = 0.f; w[151] = 0.f;
    } else {
        #pragma unroll
        for (int k = 0; k < KP; k++) w[k] = 0.f;
    }

    // precompute DSMEM addresses of my gate slot in all 4 CTAs, both buffers
    uint32_t ra[2][4];
    {
        const int tt = (tid < U) ? tid : 0;
        uint32_t l0 = smem_u32(&gates_sh[0][rank][tt]);
        uint32_t l1 = smem_u32(&gates_sh[1][rank][tt]);
        #pragma unroll
        for (uint32_t r = 0; r < 4; r++) {
            ra[0][r] = mapa_rank(l0, r);
            ra[1][r] = mapa_rank(l1, r);
        }
    }

    float c = 0.f;   // cell state, owned redundantly by tid<U in every CTA
    __syncthreads();
    cluster_sync_();

    for (int ti = 0; ti < SEQ; ti++) {
        const int t   = dir ? (SEQ - 1 - ti) : ti;
        const int buf = ti & 1;

        float zpre = 0.f;
        if (tid < U) zpre = g_Z[dir][t][rank * U + tid];

        // dot(h, w) — h from shared (broadcast), w in registers
        float acc0 = 0.f, acc1 = 0.f;
        const float4* h4 = (const float4*)h_sh;
        #pragma unroll
        for (int k = 0; k < KP / 4; k++) {
            const float4 h = h4[k];
            acc0 = fmaf(h.x, w[4 * k + 0], acc0);
            acc1 = fmaf(h.y, w[4 * k + 1], acc1);
            acc0 = fmaf(h.z, w[4 * k + 2], acc0);
            acc1 = fmaf(h.w, w[4 * k + 3], acc1);
        }
        const float z = zpre + acc0 + acc1;

        // activation (this CTA's gate) + broadcast to all 4 cluster CTAs
        if (tid < U) {
            float a;
            if (rank == 2) a = tanhf(z);
            else           a = 1.f / (1.f + expf(-z));
            st_cluster_f32(ra[buf][0], a);
            st_cluster_f32(ra[buf][1], a);
            st_cluster_f32(ra[buf][2], a);
            st_cluster_f32(ra[buf][3], a);
        }

        cluster_sync_();   // gate values visible cluster-wide

        if (tid < U) {
            const float gi = gates_sh[buf][0][tid];
            const float gf = gates_sh[buf][1][tid];
            const float gg = gates_sh[buf][2][tid];
            const float go = gates_sh[buf][3][tid];
            c = fmaf(gf, c, gi * gg);
            const float h = go * tanhf(c);
            h_sh[tid] = h;
            if (rank == 0) g_hidden[t][dir * U + tid] = h;
        }
        __syncthreads();   // h_sh ready for next step's dot
    }
}

// ============================================================================
// Kernel 3: out = hidden @ W1 + b1    [SEQ, 300]
// ============================================================================
__global__ void __launch_bounds__(320) outGemm_kernel(
    const float* __restrict__ W1, const float* __restrict__ b1)
{
    __shared__ float hrow[H1];
    const int t = blockIdx.x;
    for (int d = threadIdx.x; d < H1; d += blockDim.x) hrow[d] = g_hidden[t][d];
    __syncthreads();
    const int j = threadIdx.x;
    if (j < H1) {
        float acc = b1[j];
        #pragma unroll 4
        for (int d = 0; d < H1; d++) acc = fmaf(hrow[d], W1[d * H1 + j], acc);
        g_out[t][j] = acc;
    }
}

// ============================================================================
// Kernel 4: per-position synonym attention + h_hat + c2, accumulate H.
// grid SEQ, block 128.
// ============================================================================
__global__ void __launch_bounds__(128) syn_kernel(
    const int* __restrict__ sentence, const int* __restrict__ syn,
    const float* __restrict__ E,
    const float* __restrict__ W2, const float* __restrict__ b2)
{
    __shared__ float orow[H1];
    __shared__ float hhat[H1];
    __shared__ float red[128];
    const int s   = blockIdx.x;
    const int idx = (s == 0) ? 0 : (s - 1);
    const int tid = threadIdx.x;

    for (int d = tid; d < H1; d += 128) {
        orow[d] = g_out[idx][d];
        hhat[d] = g_hidden[idx][d];
    }
    __syncthreads();

    const int tok = sentence[s];
    #pragma unroll 1
    for (int k = 0; k < 4; k++) {
        const int st = syn[tok * 4 + k];
        const float* __restrict__ e = E + (size_t)st * D_IN;
        float p = 0.f;
        for (int d = tid; d < H1; d += 128) p = fmaf(e[d], orow[d], p);
        red[tid] = p; __syncthreads();
        #pragma unroll
        for (int o = 64; o > 0; o >>= 1) {
            if (tid < o) red[tid] += red[tid + o];
            __syncthreads();
        }
        const float coeff = expf(red[0]);
        __syncthreads();                       // red reused next iteration
        for (int d = tid; d < H1; d += 128) hhat[d] = fmaf(coeff, e[d], hhat[d]);
        __syncthreads();
    }

    // c2 = exp(tanh(hhat . W2 + b2))
    float p = 0.f;
    for (int d = tid; d < H1; d += 128) p = fmaf(hhat[d], W2[d], p);
    red[tid] = p; __syncthreads();
    #pragma unroll
    for (int o = 64; o > 0; o >>= 1) {
        if (tid < o) red[tid] += red[tid + o];
        __syncthreads();
    }
    const float c2 = expf(tanhf(red[0] + b2[0]));

    for (int d = tid; d < H1; d += 128) atomicAdd(&g_H[d], c2 * hhat[d]);
}

// ============================================================================
// Kernel 5: heads — out[0..7] = H@We + be, out[8] = H@Ws + bs
// ============================================================================
__global__ void heads_kernel(
    const float* __restrict__ We, const float* __restrict__ be,
    const float* __restrict__ Ws, const float* __restrict__ bs,
    float* __restrict__ out)
{
    const int j = threadIdx.x;
    if (j < 8) {
        float acc = be[j];
        for (int d = 0; d < H1; d++) acc = fmaf(g_H[d], We[d * 8 + j], acc);
        out[j] = acc;
    } else if (j == 8) {
        float acc = bs[0];
        for (int d = 0; d < H1; d++) acc = fmaf(g_H[d], Ws[d], acc);
        out[8] = acc;
    }
}

// ============================================================================
extern "C" void kernel_launch(void* const* d_in, const int* in_sizes, int n_in,
                              void* d_out, int out_size)
{
    const int*   sentence = (const int*)  d_in[0];
    const int*   syn      = (const int*)  d_in[1];
    const float* E        = (const float*)d_in[2];
    const float* Wk_f     = (const float*)d_in[3];
    const float* Wr_f     = (const float*)d_in[4];
    const float* b_f      = (const float*)d_in[5];
    const float* Wk_b     = (const float*)d_in[6];
    const float* Wr_b     = (const float*)d_in[7];
    const float* b_b      = (const float*)d_in[8];
    const float* W1       = (const float*)d_in[9];
    const float* b1       = (const float*)d_in[10];
    const float* W2       = (const float*)d_in[11];
    const float* b2       = (const float*)d_in[12];
    const float* We       = (const float*)d_in[13];
    const float* be       = (const float*)d_in[14];
    const float* Ws       = (const float*)d_in[15];
    const float* bs       = (const float*)d_in[16];
    float* out = (float*)d_out;

    zeroH_kernel<<<1, 320>>>();
    embZ_kernel<<<dim3(SEQ, 2), 160>>>(sentence, E, Wk_f, b_f, Wk_b, b_b);
    lstm_rec_kernel<<<dim3(4, 2), 160>>>(Wr_f, Wr_b);
    outGemm_kernel<<<SEQ, 320>>>(W1, b1);
    syn_kernel<<<SEQ, 128>>>(sentence, syn, E, W2, b2);
    heads_kernel<<<1, 32>>>(We, be, Ws, bs, out);
}